// round 9
// baseline (speedup 1.0000x reference)
#include <cuda_runtime.h>

#define NN 8192
#define VV 8
#define OO 16
#define HH 128
#define ROW (4*VV + 3*OO)   // 80 floats per input row
#define TPB 256
#define WPB 8               // warps per block
#define NPART 512           // blocks; each warp handles 2 problem rows
#define NPW 2               // problem rows (n) per warp
#define BUFCAP 64           // power-of-2 smem ring per warp

// Per-block partials (plain stores; no zeroing kernel)
__device__ float g_pd[NPART];
__device__ float g_po[NPART];
__device__ float g_pv[NPART];
__device__ int   g_oc[NPART];
__device__ int   g_vc[NPART];
__device__ unsigned int g_done;   // zero-init; last block resets each launch

__inline__ __device__ float warp_red_f(float v) {
    #pragma unroll
    for (int o = 16; o > 0; o >>= 1) v += __shfl_down_sync(0xffffffffu, v, o);
    return v;
}
__inline__ __device__ int warp_red_i(int v) {
    #pragma unroll
    for (int o = 16; o > 0; o >>= 1) v += __shfl_down_sync(0xffffffffu, v, o);
    return v;
}

__inline__ __device__ float fast_sqrt(float x) {
    float r;
    asm("sqrt.approx.f32 %0, %1;" : "=f"(r) : "f"(x));
    return r;
}

// Warp layout: lane = v*4 + ch. Vehicle v, chunk ch of 32 h-steps.
// One warp = one n at a time (NPW rows sequentially) => obstacle data,
// prune box, ring state all warp-uniform; compaction via ballot/popc.
// grid=512 => all CTAs resident in ONE wave (4 CTAs/SM cap at 63 regs).
__global__ void __launch_bounds__(TPB) loss_kernel(
    const float* __restrict__ pred,     // (N, V, H) f32
    const float* __restrict__ inputs,   // (N, 80) f32
    float* __restrict__ out)
{
    const int warp = threadIdx.x >> 5;
    const int lane = threadIdx.x & 31;
    const int v  = lane >> 2;
    const int ch = lane & 3;

    __shared__ float  s_ox[WPB][OO], s_oy[WPB][OO], s_r2[WPB][OO];
    __shared__ float2 s_buf[WPB][BUFCAP];           // drain ring

    float dist_sum = 0.0f, oinv = 0.0f, vinv = 0.0f;
    int ocnt = 0, vcnt = 0;
    const unsigned lt_mask = (1u << lane) - 1u;
    const bool vact = (v < 7);

    #pragma unroll 1
    for (int k = 0; k < NPW; ++k) {
        const int n = (blockIdx.x * WPB + warp) * NPW + k;
        const float* row = inputs + (size_t)n * ROW;

        __syncwarp();   // previous row's smem reads done before refill

        // ---- obstacles -> smem; prune box via warp reductions ----
        float lcx = 0.0f, lcy = 0.0f, lr = 0.0f;
        if (lane < OO) {
            lcx = row[4*VV + 3*lane + 0];
            lcy = row[4*VV + 3*lane + 1];
            lr  = row[4*VV + 3*lane + 2] + 1.0f;     // + OBST_RADIUS
            s_ox[warp][lane] = lcx;
            s_oy[warp][lane] = lcy;
            s_r2[warp][lane] = (lr > 0.0f) ? lr * lr : -1.0f;
        }
        float mnx = (lane < OO) ? lcx :  1e30f;
        float mxx = (lane < OO) ? lcx : -1e30f;
        float mny = (lane < OO) ? lcy :  1e30f;
        float mxy = (lane < OO) ? lcy : -1e30f;
        float rmx = (lane < OO) ? lr  : -1e30f;
        #pragma unroll
        for (int o = 16; o > 0; o >>= 1) {
            mnx = fminf(mnx, __shfl_xor_sync(0xffffffffu, mnx, o));
            mxx = fmaxf(mxx, __shfl_xor_sync(0xffffffffu, mxx, o));
            mny = fminf(mny, __shfl_xor_sync(0xffffffffu, mny, o));
            mxy = fmaxf(mxy, __shfl_xor_sync(0xffffffffu, mxy, o));
            rmx = fmaxf(rmx, __shfl_xor_sync(0xffffffffu, rmx, o));
        }
        __syncwarp();
        const float cbx = 0.5f * (mnx + mxx), hbx = 0.5f * (mxx - mnx) + rmx;
        const float cby = 0.5f * (mny + mxy), hby = 0.5f * (mxy - mny) + rmx;

        const float x0 = row[4*v + 0];
        const float y0 = row[4*v + 1];
        const float tx = row[4*v + 2];
        const float ty = row[4*v + 3];

        const float4* p4 =
            (const float4*)(pred + ((size_t)(n * VV + v) * HH + ch * 32));

        // ---- pass 1: chunk sums of cos/sin ----
        float sx = 0.0f, sy = 0.0f;
        #pragma unroll
        for (int i = 0; i < 8; ++i) {
            float4 p = p4[i];
            float s, c;
            __sincosf(p.x, &s, &c); sx += c; sy += s;
            __sincosf(p.y, &s, &c); sx += c; sy += s;
            __sincosf(p.z, &s, &c); sx += c; sy += s;
            __sincosf(p.w, &s, &c); sx += c; sy += s;
        }
        // segmented exclusive prefix over the 4 chunk-lanes of each vehicle
        float ix = sx, iy = sy, t;
        t = __shfl_up_sync(0xffffffffu, ix, 1, 4); if (ch >= 1) ix += t;
        t = __shfl_up_sync(0xffffffffu, iy, 1, 4); if (ch >= 1) iy += t;
        t = __shfl_up_sync(0xffffffffu, ix, 2, 4); if (ch >= 2) ix += t;
        t = __shfl_up_sync(0xffffffffu, iy, 2, 4); if (ch >= 2) iy += t;
        float x = fmaf(2.0f, ix - sx, x0);   // STEP = 2
        float y = fmaf(2.0f, iy - sy, y0);

        // ---- pass 2: walk 32 steps; compact in-box; drain inline ----
        int head = 0, pending = 0;           // warp-uniform ring state

        #pragma unroll 1
        for (int i = 0; i < 8; ++i) {
            float4 p = p4[i];
            float pv[4] = {p.x, p.y, p.z, p.w};
            #pragma unroll
            for (int j = 0; j < 4; ++j) {
                float s, c;
                __sincosf(pv[j], &s, &c);
                x = fmaf(2.0f, c, x);
                y = fmaf(2.0f, s, y);

                // target-distance term
                float dx = tx - x, dy = ty - y;
                dist_sum += fast_sqrt(fmaf(dx, dx, dy * dy));

                // in-box -> compact append to ring
                bool inbox = (fabsf(x - cbx) <= hbx) & (fabsf(y - cby) <= hby);
                unsigned m = __ballot_sync(0xffffffffu, inbox);
                if (inbox)
                    s_buf[warp][(head + pending + __popc(m & lt_mask)) & (BUFCAP-1)] =
                        make_float2(x, y);
                pending += __popc(m);

                // vehicle-vehicle term: vehicle v+1 same chunk = lane+4
                float xn = __shfl_down_sync(0xffffffffu, x, 4);
                float yn = __shfl_down_sync(0xffffffffu, y, 4);
                if (vact) {
                    float bxv = xn - x, byv = yn - y;
                    float d2 = fmaf(bxv, bxv, byv * byv);
                    if (d2 < 1.0f) { vinv += rsqrtf(d2); vcnt++; } // VEH_R^2=1
                }

                // dense drain of 32 points (warp-uniform branch)
                if (pending >= 32) {
                    __syncwarp();
                    float2 q = s_buf[warp][(head + lane) & (BUFCAP-1)];
                    #pragma unroll
                    for (int o = 0; o < OO; ++o) {
                        float ax = q.x - s_ox[warp][o];
                        float ay = q.y - s_oy[warp][o];
                        float d2o = fmaf(ax, ax, ay * ay);
                        if (d2o < s_r2[warp][o]) { oinv += rsqrtf(d2o); ocnt++; }
                    }
                    head = (head + 32) & (BUFCAP-1);
                    pending -= 32;
                }
            }
        }

        // final flush of the partial ring
        if (pending > 0) {
            __syncwarp();
            if (lane < pending) {
                float2 q = s_buf[warp][(head + lane) & (BUFCAP-1)];
                #pragma unroll
                for (int o = 0; o < OO; ++o) {
                    float ax = q.x - s_ox[warp][o];
                    float ay = q.y - s_oy[warp][o];
                    float d2o = fmaf(ax, ax, ay * ay);
                    if (d2o < s_r2[warp][o]) { oinv += rsqrtf(d2o); ocnt++; }
                }
            }
        }
    }

    // ---- warp -> block reduction ----
    dist_sum = warp_red_f(dist_sum);
    oinv     = warp_red_f(oinv);
    vinv     = warp_red_f(vinv);
    ocnt     = warp_red_i(ocnt);
    vcnt     = warp_red_i(vcnt);

    __shared__ float sd[WPB], so[WPB], sv[WPB];
    __shared__ int soc[WPB], svc[WPB];
    if (lane == 0) {
        sd[warp] = dist_sum; so[warp] = oinv; sv[warp] = vinv;
        soc[warp] = ocnt; svc[warp] = vcnt;
    }
    __syncthreads();
    if (warp == 0) {
        float d = (lane < WPB) ? sd[lane] : 0.0f;
        float a = (lane < WPB) ? so[lane] : 0.0f;
        float b = (lane < WPB) ? sv[lane] : 0.0f;
        int   c = (lane < WPB) ? soc[lane] : 0;
        int   e = (lane < WPB) ? svc[lane] : 0;
        d = warp_red_f(d); a = warp_red_f(a); b = warp_red_f(b);
        c = warp_red_i(c); e = warp_red_i(e);
        if (lane == 0) {
            g_pd[blockIdx.x] = d;
            g_po[blockIdx.x] = a;
            g_pv[blockIdx.x] = b;
            g_oc[blockIdx.x] = c;
            g_vc[blockIdx.x] = e;
        }
    }

    // ---- last-block finalize ----
    __shared__ bool isLast;
    __threadfence();
    if (threadIdx.x == 0) {
        unsigned int prev = atomicAdd(&g_done, 1u);
        isLast = (prev == NPART - 1);
    }
    __syncthreads();
    if (!isLast) return;

    float d = 0.0f, a = 0.0f, b = 0.0f;
    int c = 0, e = 0;
    #pragma unroll
    for (int i = 0; i < NPART / TPB; ++i) {
        int idx = threadIdx.x + i * TPB;
        d += g_pd[idx]; a += g_po[idx]; b += g_pv[idx];
        c += g_oc[idx]; e += g_vc[idx];
    }
    d = warp_red_f(d); a = warp_red_f(a); b = warp_red_f(b);
    c = warp_red_i(c); e = warp_red_i(e);
    if (lane == 0) {
        sd[warp] = d; so[warp] = a; sv[warp] = b; soc[warp] = c; svc[warp] = e;
    }
    __syncthreads();
    if (warp == 0) {
        d = (lane < WPB) ? sd[lane] : 0.0f;
        a = (lane < WPB) ? so[lane] : 0.0f;
        b = (lane < WPB) ? sv[lane] : 0.0f;
        c = (lane < WPB) ? soc[lane] : 0;
        e = (lane < WPB) ? svc[lane] : 0;
        d = warp_red_f(d); a = warp_red_f(a); b = warp_red_f(b);
        c = warp_red_i(c); e = warp_red_i(e);
        if (lane == 0) {
            double loss = (double)d / ((double)NN * VV * HH);   // DIST_COST=1
            if (c > 0) loss += ((double)a / (double)c) * 0.1;   // OBST_COST
            if (e > 0) loss += ((double)b / (double)e) * 0.1;   // VEH_COST
            out[0] = (float)loss;
            g_done = 0;   // reset for next graph replay
        }
    }
}

extern "C" void kernel_launch(void* const* d_in, const int* in_sizes, int n_in,
                              void* d_out, int out_size) {
    const float* pred   = (const float*)d_in[0];   // (N, V, H, 1) f32
    const float* inputs = (const float*)d_in[1];   // (N, 80) f32
    float* out = (float*)d_out;

    loss_kernel<<<NPART, TPB>>>(pred, inputs, out);
}

// round 10
// speedup vs baseline: 1.0073x; 1.0073x over previous
#include <cuda_runtime.h>

#define NN 8192
#define VV 8
#define OO 16
#define HH 128
#define ROW (4*VV + 3*OO)   // 80 floats per input row
#define TPB 256
#define WPB 8               // warps per block (1 warp = 1 problem row n)
#define NPART (NN / WPB)    // 1024 blocks
#define BUFCAP 64           // power-of-2 smem ring per warp

// Per-block partials (plain stores; no zeroing kernel)
__device__ float g_pd[NPART];
__device__ float g_po[NPART];
__device__ float g_pv[NPART];
__device__ int   g_oc[NPART];
__device__ int   g_vc[NPART];
__device__ unsigned int g_done;   // zero-init; last block resets each launch

__inline__ __device__ float warp_red_f(float v) {
    #pragma unroll
    for (int o = 16; o > 0; o >>= 1) v += __shfl_down_sync(0xffffffffu, v, o);
    return v;
}
__inline__ __device__ int warp_red_i(int v) {
    #pragma unroll
    for (int o = 16; o > 0; o >>= 1) v += __shfl_down_sync(0xffffffffu, v, o);
    return v;
}

__inline__ __device__ float fast_sqrt(float x) {
    float r;
    asm("sqrt.approx.f32 %0, %1;" : "=f"(r) : "f"(x));
    return r;
}

// Warp layout: lane = v*4 + ch. Vehicle v, chunk ch of 32 h-steps.
// One warp = one n => obstacle data, prune box, ring state warp-uniform.
// __launch_bounds__(256,5): force ~48 regs -> 5 CTAs/SM -> 40 warps/SM.
__global__ void __launch_bounds__(TPB, 5) loss_kernel(
    const float* __restrict__ pred,     // (N, V, H) f32
    const float* __restrict__ inputs,   // (N, 80) f32
    float* __restrict__ out)
{
    const int warp = threadIdx.x >> 5;
    const int lane = threadIdx.x & 31;
    const int n  = blockIdx.x * WPB + warp;
    const int v  = lane >> 2;
    const int ch = lane & 3;

    const float* row = inputs + (size_t)n * ROW;

    __shared__ float  s_ox[WPB][OO], s_oy[WPB][OO], s_r2[WPB][OO];
    __shared__ float2 s_buf[WPB][BUFCAP];           // drain ring

    // ---- obstacles -> smem; prune box via warp reductions ----
    float lcx = 0.0f, lcy = 0.0f, lr = 0.0f;
    if (lane < OO) {
        lcx = row[4*VV + 3*lane + 0];
        lcy = row[4*VV + 3*lane + 1];
        lr  = row[4*VV + 3*lane + 2] + 1.0f;     // + OBST_RADIUS
        s_ox[warp][lane] = lcx;
        s_oy[warp][lane] = lcy;
        s_r2[warp][lane] = (lr > 0.0f) ? lr * lr : -1.0f;
    }
    float mnx = (lane < OO) ? lcx :  1e30f;
    float mxx = (lane < OO) ? lcx : -1e30f;
    float mny = (lane < OO) ? lcy :  1e30f;
    float mxy = (lane < OO) ? lcy : -1e30f;
    float rmx = (lane < OO) ? lr  : -1e30f;
    #pragma unroll
    for (int o = 16; o > 0; o >>= 1) {
        mnx = fminf(mnx, __shfl_xor_sync(0xffffffffu, mnx, o));
        mxx = fmaxf(mxx, __shfl_xor_sync(0xffffffffu, mxx, o));
        mny = fminf(mny, __shfl_xor_sync(0xffffffffu, mny, o));
        mxy = fmaxf(mxy, __shfl_xor_sync(0xffffffffu, mxy, o));
        rmx = fmaxf(rmx, __shfl_xor_sync(0xffffffffu, rmx, o));
    }
    __syncwarp();
    const float cbx = 0.5f * (mnx + mxx), hbx = 0.5f * (mxx - mnx) + rmx;
    const float cby = 0.5f * (mny + mxy), hby = 0.5f * (mxy - mny) + rmx;

    const float x0 = row[4*v + 0];
    const float y0 = row[4*v + 1];
    const float tx = row[4*v + 2];
    const float ty = row[4*v + 3];

    const float4* p4 =
        (const float4*)(pred + ((size_t)(n * VV + v) * HH + ch * 32));

    // ---- pass 1: chunk sums of cos/sin ----
    float sx = 0.0f, sy = 0.0f;
    #pragma unroll
    for (int i = 0; i < 8; ++i) {
        float4 p = p4[i];
        float s, c;
        __sincosf(p.x, &s, &c); sx += c; sy += s;
        __sincosf(p.y, &s, &c); sx += c; sy += s;
        __sincosf(p.z, &s, &c); sx += c; sy += s;
        __sincosf(p.w, &s, &c); sx += c; sy += s;
    }
    // segmented exclusive prefix over the 4 chunk-lanes of each vehicle
    float ix = sx, iy = sy, t;
    t = __shfl_up_sync(0xffffffffu, ix, 1, 4); if (ch >= 1) ix += t;
    t = __shfl_up_sync(0xffffffffu, iy, 1, 4); if (ch >= 1) iy += t;
    t = __shfl_up_sync(0xffffffffu, ix, 2, 4); if (ch >= 2) ix += t;
    t = __shfl_up_sync(0xffffffffu, iy, 2, 4); if (ch >= 2) iy += t;
    float x = fmaf(2.0f, ix - sx, x0);   // STEP = 2
    float y = fmaf(2.0f, iy - sy, y0);

    // ---- pass 2: walk 32 steps; compact in-box; drain inline ----
    float dist_sum = 0.0f, oinv = 0.0f, vinv = 0.0f;
    int ocnt = 0, vcnt = 0;
    int head = 0, pending = 0;              // warp-uniform ring state
    const unsigned lt_mask = (1u << lane) - 1u;
    const bool vact = (v < 7);

    #pragma unroll 1
    for (int i = 0; i < 8; ++i) {
        float4 p = p4[i];
        #pragma unroll
        for (int j = 0; j < 4; ++j) {
            float ang = (j == 0) ? p.x : (j == 1) ? p.y : (j == 2) ? p.z : p.w;
            float s, c;
            __sincosf(ang, &s, &c);
            x = fmaf(2.0f, c, x);
            y = fmaf(2.0f, s, y);

            // target-distance term
            float dx = tx - x, dy = ty - y;
            dist_sum += fast_sqrt(fmaf(dx, dx, dy * dy));

            // in-box -> compact append to ring
            bool inbox = (fabsf(x - cbx) <= hbx) & (fabsf(y - cby) <= hby);
            unsigned m = __ballot_sync(0xffffffffu, inbox);
            if (inbox)
                s_buf[warp][(head + pending + __popc(m & lt_mask)) & (BUFCAP-1)] =
                    make_float2(x, y);
            pending += __popc(m);

            // vehicle-vehicle term: vehicle v+1 same chunk = lane+4
            float xn = __shfl_down_sync(0xffffffffu, x, 4);
            float yn = __shfl_down_sync(0xffffffffu, y, 4);
            if (vact) {
                float bxv = xn - x, byv = yn - y;
                float d2 = fmaf(bxv, bxv, byv * byv);
                if (d2 < 1.0f) { vinv += rsqrtf(d2); vcnt++; }  // VEH_R^2 = 1
            }

            // dense drain of 32 points (warp-uniform branch)
            if (pending >= 32) {
                __syncwarp();
                float2 q = s_buf[warp][(head + lane) & (BUFCAP-1)];
                #pragma unroll
                for (int o = 0; o < OO; ++o) {
                    float ax = q.x - s_ox[warp][o];
                    float ay = q.y - s_oy[warp][o];
                    float d2o = fmaf(ax, ax, ay * ay);
                    if (d2o < s_r2[warp][o]) { oinv += rsqrtf(d2o); ocnt++; }
                }
                head = (head + 32) & (BUFCAP-1);
                pending -= 32;
            }
        }
    }

    // final flush of the partial ring
    if (pending > 0) {
        __syncwarp();
        if (lane < pending) {
            float2 q = s_buf[warp][(head + lane) & (BUFCAP-1)];
            #pragma unroll
            for (int o = 0; o < OO; ++o) {
                float ax = q.x - s_ox[warp][o];
                float ay = q.y - s_oy[warp][o];
                float d2o = fmaf(ax, ax, ay * ay);
                if (d2o < s_r2[warp][o]) { oinv += rsqrtf(d2o); ocnt++; }
            }
        }
    }

    // ---- warp -> block reduction ----
    dist_sum = warp_red_f(dist_sum);
    oinv     = warp_red_f(oinv);
    vinv     = warp_red_f(vinv);
    ocnt     = warp_red_i(ocnt);
    vcnt     = warp_red_i(vcnt);

    __shared__ float sd[WPB], so[WPB], sv[WPB];
    __shared__ int soc[WPB], svc[WPB];
    if (lane == 0) {
        sd[warp] = dist_sum; so[warp] = oinv; sv[warp] = vinv;
        soc[warp] = ocnt; svc[warp] = vcnt;
    }
    __syncthreads();
    if (warp == 0) {
        float d = (lane < WPB) ? sd[lane] : 0.0f;
        float a = (lane < WPB) ? so[lane] : 0.0f;
        float b = (lane < WPB) ? sv[lane] : 0.0f;
        int   c = (lane < WPB) ? soc[lane] : 0;
        int   e = (lane < WPB) ? svc[lane] : 0;
        d = warp_red_f(d); a = warp_red_f(a); b = warp_red_f(b);
        c = warp_red_i(c); e = warp_red_i(e);
        if (lane == 0) {
            g_pd[blockIdx.x] = d;
            g_po[blockIdx.x] = a;
            g_pv[blockIdx.x] = b;
            g_oc[blockIdx.x] = c;
            g_vc[blockIdx.x] = e;
        }
    }

    // ---- last-block finalize ----
    __shared__ bool isLast;
    __threadfence();
    if (threadIdx.x == 0) {
        unsigned int prev = atomicAdd(&g_done, 1u);
        isLast = (prev == NPART - 1);
    }
    __syncthreads();
    if (!isLast) return;

    float d = 0.0f, a = 0.0f, b = 0.0f;
    int c = 0, e = 0;
    #pragma unroll
    for (int i = 0; i < NPART / TPB; ++i) {
        int idx = threadIdx.x + i * TPB;
        d += g_pd[idx]; a += g_po[idx]; b += g_pv[idx];
        c += g_oc[idx]; e += g_vc[idx];
    }
    d = warp_red_f(d); a = warp_red_f(a); b = warp_red_f(b);
    c = warp_red_i(c); e = warp_red_i(e);
    if (lane == 0) {
        sd[warp] = d; so[warp] = a; sv[warp] = b; soc[warp] = c; svc[warp] = e;
    }
    __syncthreads();
    if (warp == 0) {
        d = (lane < WPB) ? sd[lane] : 0.0f;
        a = (lane < WPB) ? so[lane] : 0.0f;
        b = (lane < WPB) ? sv[lane] : 0.0f;
        c = (lane < WPB) ? soc[lane] : 0;
        e = (lane < WPB) ? svc[lane] : 0;
        d = warp_red_f(d); a = warp_red_f(a); b = warp_red_f(b);
        c = warp_red_i(c); e = warp_red_i(e);
        if (lane == 0) {
            double loss = (double)d / ((double)NN * VV * HH);   // DIST_COST=1
            if (c > 0) loss += ((double)a / (double)c) * 0.1;   // OBST_COST
            if (e > 0) loss += ((double)b / (double)e) * 0.1;   // VEH_COST
            out[0] = (float)loss;
            g_done = 0;   // reset for next graph replay
        }
    }
}

extern "C" void kernel_launch(void* const* d_in, const int* in_sizes, int n_in,
                              void* d_out, int out_size) {
    const float* pred   = (const float*)d_in[0];   // (N, V, H, 1) f32
    const float* inputs = (const float*)d_in[1];   // (N, 80) f32
    float* out = (float*)d_out;

    loss_kernel<<<NPART, TPB>>>(pred, inputs, out);
}

// round 11
// speedup vs baseline: 1.1222x; 1.1140x over previous
#include <cuda_runtime.h>

#define NN 8192
#define VV 8
#define OO 16
#define HH 128
#define ROW (4*VV + 3*OO)   // 80 floats per input row
#define TPB 256
#define WPB 8               // warps per block (1 warp = 1 problem row n)
#define NPART (NN / WPB)    // 1024 blocks
#define BUFCAP 256          // power-of-2 smem ring per warp (max pending 159)

// Per-block partials (plain stores; no zeroing kernel)
__device__ float g_pd[NPART];
__device__ float g_po[NPART];
__device__ float g_pv[NPART];
__device__ int   g_oc[NPART];
__device__ int   g_vc[NPART];
__device__ unsigned int g_done;   // zero-init; last block resets each launch

__inline__ __device__ float warp_red_f(float v) {
    #pragma unroll
    for (int o = 16; o > 0; o >>= 1) v += __shfl_down_sync(0xffffffffu, v, o);
    return v;
}
__inline__ __device__ int warp_red_i(int v) {
    #pragma unroll
    for (int o = 16; o > 0; o >>= 1) v += __shfl_down_sync(0xffffffffu, v, o);
    return v;
}

__inline__ __device__ float fast_sqrt(float x) {
    float r;
    asm("sqrt.approx.f32 %0, %1;" : "=f"(r) : "f"(x));
    return r;
}

// Warp layout: lane = v*4 + ch. Vehicle v, chunk ch of 32 h-steps.
// One warp = one n => obstacle data, prune box, ring state warp-uniform.
// Inner loop batches the convergent ops (ballot/shfl/drain-check) per 4
// steps so their latencies pipeline instead of serializing the warp.
__global__ void __launch_bounds__(TPB) loss_kernel(
    const float* __restrict__ pred,     // (N, V, H) f32
    const float* __restrict__ inputs,   // (N, 80) f32
    float* __restrict__ out)
{
    const int warp = threadIdx.x >> 5;
    const int lane = threadIdx.x & 31;
    const int n  = blockIdx.x * WPB + warp;
    const int v  = lane >> 2;
    const int ch = lane & 3;

    const float* row = inputs + (size_t)n * ROW;

    __shared__ float  s_ox[WPB][OO], s_oy[WPB][OO], s_r2[WPB][OO];
    __shared__ float2 s_buf[WPB][BUFCAP];           // drain ring

    // ---- obstacles -> smem; prune box via warp reductions ----
    float lcx = 0.0f, lcy = 0.0f, lr = 0.0f;
    if (lane < OO) {
        lcx = row[4*VV + 3*lane + 0];
        lcy = row[4*VV + 3*lane + 1];
        lr  = row[4*VV + 3*lane + 2] + 1.0f;     // + OBST_RADIUS
        s_ox[warp][lane] = lcx;
        s_oy[warp][lane] = lcy;
        s_r2[warp][lane] = (lr > 0.0f) ? lr * lr : -1.0f;
    }
    float mnx = (lane < OO) ? lcx :  1e30f;
    float mxx = (lane < OO) ? lcx : -1e30f;
    float mny = (lane < OO) ? lcy :  1e30f;
    float mxy = (lane < OO) ? lcy : -1e30f;
    float rmx = (lane < OO) ? lr  : -1e30f;
    #pragma unroll
    for (int o = 16; o > 0; o >>= 1) {
        mnx = fminf(mnx, __shfl_xor_sync(0xffffffffu, mnx, o));
        mxx = fmaxf(mxx, __shfl_xor_sync(0xffffffffu, mxx, o));
        mny = fminf(mny, __shfl_xor_sync(0xffffffffu, mny, o));
        mxy = fmaxf(mxy, __shfl_xor_sync(0xffffffffu, mxy, o));
        rmx = fmaxf(rmx, __shfl_xor_sync(0xffffffffu, rmx, o));
    }
    __syncwarp();
    const float cbx = 0.5f * (mnx + mxx), hbx = 0.5f * (mxx - mnx) + rmx;
    const float cby = 0.5f * (mny + mxy), hby = 0.5f * (mxy - mny) + rmx;

    const float x0 = row[4*v + 0];
    const float y0 = row[4*v + 1];
    const float tx = row[4*v + 2];
    const float ty = row[4*v + 3];

    const float4* p4 =
        (const float4*)(pred + ((size_t)(n * VV + v) * HH + ch * 32));

    // ---- pass 1: chunk sums of cos/sin ----
    float sx = 0.0f, sy = 0.0f;
    #pragma unroll
    for (int i = 0; i < 8; ++i) {
        float4 p = p4[i];
        float s, c;
        __sincosf(p.x, &s, &c); sx += c; sy += s;
        __sincosf(p.y, &s, &c); sx += c; sy += s;
        __sincosf(p.z, &s, &c); sx += c; sy += s;
        __sincosf(p.w, &s, &c); sx += c; sy += s;
    }
    // segmented exclusive prefix over the 4 chunk-lanes of each vehicle
    float ix = sx, iy = sy, t;
    t = __shfl_up_sync(0xffffffffu, ix, 1, 4); if (ch >= 1) ix += t;
    t = __shfl_up_sync(0xffffffffu, iy, 1, 4); if (ch >= 1) iy += t;
    t = __shfl_up_sync(0xffffffffu, ix, 2, 4); if (ch >= 2) ix += t;
    t = __shfl_up_sync(0xffffffffu, iy, 2, 4); if (ch >= 2) iy += t;
    float x = fmaf(2.0f, ix - sx, x0);   // STEP = 2
    float y = fmaf(2.0f, iy - sy, y0);

    // ---- pass 2: 8 batches of 4 steps; convergent ops batched ----
    float dist_sum = 0.0f, oinv = 0.0f, vinv = 0.0f;
    int ocnt = 0, vcnt = 0;
    int head = 0, pending = 0;              // warp-uniform ring state
    const unsigned lt_mask = (1u << lane) - 1u;
    const bool vact = (v < 7);

    #pragma unroll 1
    for (int i = 0; i < 8; ++i) {
        float4 p = p4[i];

        // serial position chain (unavoidable), positions kept per step
        float xs[4], ys[4];
        {
            float s, c;
            __sincosf(p.x, &s, &c);
            x = fmaf(2.0f, c, x); y = fmaf(2.0f, s, y); xs[0] = x; ys[0] = y;
            __sincosf(p.y, &s, &c);
            x = fmaf(2.0f, c, x); y = fmaf(2.0f, s, y); xs[1] = x; ys[1] = y;
            __sincosf(p.z, &s, &c);
            x = fmaf(2.0f, c, x); y = fmaf(2.0f, s, y); xs[2] = x; ys[2] = y;
            __sincosf(p.w, &s, &c);
            x = fmaf(2.0f, c, x); y = fmaf(2.0f, s, y); xs[3] = x; ys[3] = y;
        }

        // batched target-distance terms (independent)
        #pragma unroll
        for (int j = 0; j < 4; ++j) {
            float dx = tx - xs[j], dy = ty - ys[j];
            dist_sum += fast_sqrt(fmaf(dx, dx, dy * dy));
        }

        // batched in-box tests + back-to-back ballots
        bool ib[4];
        unsigned m[4];
        #pragma unroll
        for (int j = 0; j < 4; ++j)
            ib[j] = (fabsf(xs[j] - cbx) <= hbx) & (fabsf(ys[j] - cby) <= hby);
        #pragma unroll
        for (int j = 0; j < 4; ++j)
            m[j] = __ballot_sync(0xffffffffu, ib[j]);

        // appends (ring, warp-uniform base)
        #pragma unroll
        for (int j = 0; j < 4; ++j) {
            if (ib[j])
                s_buf[warp][(head + pending + __popc(m[j] & lt_mask)) & (BUFCAP-1)] =
                    make_float2(xs[j], ys[j]);
            pending += __popc(m[j]);
        }

        // batched vehicle shfls (8 independent), then vehicle terms
        float xn[4], yn[4];
        #pragma unroll
        for (int j = 0; j < 4; ++j) {
            xn[j] = __shfl_down_sync(0xffffffffu, xs[j], 4);
            yn[j] = __shfl_down_sync(0xffffffffu, ys[j], 4);
        }
        if (vact) {
            #pragma unroll
            for (int j = 0; j < 4; ++j) {
                float bxv = xn[j] - xs[j], byv = yn[j] - ys[j];
                float d2 = fmaf(bxv, bxv, byv * byv);
                if (d2 < 1.0f) { vinv += rsqrtf(d2); vcnt++; }  // VEH_R^2 = 1
            }
        }

        // drain check once per 4 steps (warp-uniform while)
        while (pending >= 32) {
            __syncwarp();
            float2 q = s_buf[warp][(head + lane) & (BUFCAP-1)];
            #pragma unroll
            for (int o = 0; o < OO; ++o) {
                float ax = q.x - s_ox[warp][o];
                float ay = q.y - s_oy[warp][o];
                float d2o = fmaf(ax, ax, ay * ay);
                if (d2o < s_r2[warp][o]) { oinv += rsqrtf(d2o); ocnt++; }
            }
            head = (head + 32) & (BUFCAP-1);
            pending -= 32;
        }
    }

    // final flush of the partial ring
    if (pending > 0) {
        __syncwarp();
        if (lane < pending) {
            float2 q = s_buf[warp][(head + lane) & (BUFCAP-1)];
            #pragma unroll
            for (int o = 0; o < OO; ++o) {
                float ax = q.x - s_ox[warp][o];
                float ay = q.y - s_oy[warp][o];
                float d2o = fmaf(ax, ax, ay * ay);
                if (d2o < s_r2[warp][o]) { oinv += rsqrtf(d2o); ocnt++; }
            }
        }
    }

    // ---- warp -> block reduction ----
    dist_sum = warp_red_f(dist_sum);
    oinv     = warp_red_f(oinv);
    vinv     = warp_red_f(vinv);
    ocnt     = warp_red_i(ocnt);
    vcnt     = warp_red_i(vcnt);

    __shared__ float sd[WPB], so[WPB], sv[WPB];
    __shared__ int soc[WPB], svc[WPB];
    if (lane == 0) {
        sd[warp] = dist_sum; so[warp] = oinv; sv[warp] = vinv;
        soc[warp] = ocnt; svc[warp] = vcnt;
    }
    __syncthreads();
    if (warp == 0) {
        float d = (lane < WPB) ? sd[lane] : 0.0f;
        float a = (lane < WPB) ? so[lane] : 0.0f;
        float b = (lane < WPB) ? sv[lane] : 0.0f;
        int   c = (lane < WPB) ? soc[lane] : 0;
        int   e = (lane < WPB) ? svc[lane] : 0;
        d = warp_red_f(d); a = warp_red_f(a); b = warp_red_f(b);
        c = warp_red_i(c); e = warp_red_i(e);
        if (lane == 0) {
            g_pd[blockIdx.x] = d;
            g_po[blockIdx.x] = a;
            g_pv[blockIdx.x] = b;
            g_oc[blockIdx.x] = c;
            g_vc[blockIdx.x] = e;
        }
    }

    // ---- last-block finalize ----
    __shared__ bool isLast;
    __threadfence();
    if (threadIdx.x == 0) {
        unsigned int prev = atomicAdd(&g_done, 1u);
        isLast = (prev == NPART - 1);
    }
    __syncthreads();
    if (!isLast) return;

    float d = 0.0f, a = 0.0f, b = 0.0f;
    int c = 0, e = 0;
    #pragma unroll
    for (int i = 0; i < NPART / TPB; ++i) {
        int idx = threadIdx.x + i * TPB;
        d += g_pd[idx]; a += g_po[idx]; b += g_pv[idx];
        c += g_oc[idx]; e += g_vc[idx];
    }
    d = warp_red_f(d); a = warp_red_f(a); b = warp_red_f(b);
    c = warp_red_i(c); e = warp_red_i(e);
    if (lane == 0) {
        sd[warp] = d; so[warp] = a; sv[warp] = b; soc[warp] = c; svc[warp] = e;
    }
    __syncthreads();
    if (warp == 0) {
        d = (lane < WPB) ? sd[lane] : 0.0f;
        a = (lane < WPB) ? so[lane] : 0.0f;
        b = (lane < WPB) ? sv[lane] : 0.0f;
        c = (lane < WPB) ? soc[lane] : 0;
        e = (lane < WPB) ? svc[lane] : 0;
        d = warp_red_f(d); a = warp_red_f(a); b = warp_red_f(b);
        c = warp_red_i(c); e = warp_red_i(e);
        if (lane == 0) {
            double loss = (double)d / ((double)NN * VV * HH);   // DIST_COST=1
            if (c > 0) loss += ((double)a / (double)c) * 0.1;   // OBST_COST
            if (e > 0) loss += ((double)b / (double)e) * 0.1;   // VEH_COST
            out[0] = (float)loss;
            g_done = 0;   // reset for next graph replay
        }
    }
}

extern "C" void kernel_launch(void* const* d_in, const int* in_sizes, int n_in,
                              void* d_out, int out_size) {
    const float* pred   = (const float*)d_in[0];   // (N, V, H, 1) f32
    const float* inputs = (const float*)d_in[1];   // (N, 80) f32
    float* out = (float*)d_out;

    loss_kernel<<<NPART, TPB>>>(pred, inputs, out);
}

// round 12
// speedup vs baseline: 1.1843x; 1.0554x over previous
#include <cuda_runtime.h>

#define NN 8192
#define VV 8
#define OO 16
#define HH 128
#define ROW (4*VV + 3*OO)   // 80 floats per input row
#define TPB 128
#define WPB 4               // warps per block
#define NPW 4               // problem rows (n) per warp: lane = ng*8 + v
#define NPART (NN / (WPB * NPW))   // 512 blocks
#define BUFCAP 256          // power-of-2 ring (max pending 31+128=159)
#define OPAD 17             // obstacle array pad: 17g+o conflict-free

// Per-block partials (plain stores; no zeroing kernel)
__device__ float g_pd[NPART];
__device__ float g_po[NPART];
__device__ float g_pv[NPART];
__device__ int   g_oc[NPART];
__device__ int   g_vc[NPART];
__device__ unsigned int g_done;   // zero-init; last block resets each launch

__inline__ __device__ float warp_red_f(float v) {
    #pragma unroll
    for (int o = 16; o > 0; o >>= 1) v += __shfl_down_sync(0xffffffffu, v, o);
    return v;
}
__inline__ __device__ int warp_red_i(int v) {
    #pragma unroll
    for (int o = 16; o > 0; o >>= 1) v += __shfl_down_sync(0xffffffffu, v, o);
    return v;
}

__inline__ __device__ float fast_sqrt(float x) {
    float r;
    asm("sqrt.approx.f32 %0, %1;" : "=f"(r) : "f"(x));
    return r;
}

// One thread = one (n, v), walking all 128 steps serially (the chain is only
// an FMA: angles come from memory). Warp = 4 n-groups x 8 vehicles.
// No pass-1 / prefix scan: sincos computed exactly once per step.
__global__ void __launch_bounds__(TPB) loss_kernel(
    const float* __restrict__ pred,     // (N, V, H) f32
    const float* __restrict__ inputs,   // (N, 80) f32
    float* __restrict__ out)
{
    const int warp = threadIdx.x >> 5;
    const int lane = threadIdx.x & 31;
    const int ng   = lane >> 3;          // n-group within warp (0..3)
    const int v    = lane & 7;           // vehicle
    const int n    = (blockIdx.x * WPB + warp) * NPW + ng;

    const float* row = inputs + (size_t)n * ROW;

    __shared__ float s_ox[WPB][NPW][OPAD];
    __shared__ float s_oy[WPB][NPW][OPAD];
    __shared__ float s_r2[WPB][NPW][OPAD];
    __shared__ float2 s_buf[WPB][BUFCAP];
    __shared__ unsigned char s_grp[WPB][BUFCAP];

    // ---- obstacles -> smem (64 obstacle slots, 2 per lane) ----
    #pragma unroll
    for (int idx = lane; idx < NPW * OO; idx += 32) {
        int g = idx >> 4, o = idx & 15;
        const float* orow = inputs + (size_t)((blockIdx.x * WPB + warp) * NPW + g) * ROW
                            + 4 * VV + 3 * o;
        float cx = orow[0], cy = orow[1];
        float r  = orow[2] + 1.0f;               // + OBST_RADIUS
        s_ox[warp][g][o] = cx;
        s_oy[warp][g][o] = cy;
        s_r2[warp][g][o] = (r > 0.0f) ? r * r : -1.0f;
    }
    __syncwarp();

    // ---- per-lane prune box for its own n-group (broadcast LDS reads) ----
    float mnx = 1e30f, mxx = -1e30f, mny = 1e30f, mxy = -1e30f, rmx = -1e30f;
    #pragma unroll
    for (int o = 0; o < OO; ++o) {
        float cx = s_ox[warp][ng][o];
        float cy = s_oy[warp][ng][o];
        float r2 = s_r2[warp][ng][o];
        mnx = fminf(mnx, cx); mxx = fmaxf(mxx, cx);
        mny = fminf(mny, cy); mxy = fmaxf(mxy, cy);
        rmx = fmaxf(rmx, r2);
    }
    rmx = (rmx > 0.0f) ? fast_sqrt(rmx) : 0.0f;   // max effective radius
    const float cbx = 0.5f * (mnx + mxx), hbx = 0.5f * (mxx - mnx) + rmx;
    const float cby = 0.5f * (mny + mxy), hby = 0.5f * (mxy - mny) + rmx;

    // ---- vehicle start / target (vectorized: 16B-aligned) ----
    const float4 vd = *(const float4*)(row + 4 * v);
    float x = vd.x, y = vd.y;
    const float tx = vd.z, ty = vd.w;

    const float4* p4 = (const float4*)(pred + (size_t)(n * VV + v) * HH);

    // ---- single pass: 32 batches of 4 steps ----
    float dist_sum = 0.0f, oinv = 0.0f, vinv = 0.0f;
    int ocnt = 0, vcnt = 0;
    int head = 0, pending = 0;              // warp-uniform ring state
    const unsigned lt_mask = (1u << lane) - 1u;
    const bool vact = (v < 7);

    #pragma unroll 1
    for (int i = 0; i < HH / 4; ++i) {
        float4 p = p4[i];

        // serial position chain: only the fmaf is dependent (lat 4)
        float xs[4], ys[4];
        {
            float s, c;
            __sincosf(p.x, &s, &c);
            x = fmaf(2.0f, c, x); y = fmaf(2.0f, s, y); xs[0] = x; ys[0] = y;
            __sincosf(p.y, &s, &c);
            x = fmaf(2.0f, c, x); y = fmaf(2.0f, s, y); xs[1] = x; ys[1] = y;
            __sincosf(p.z, &s, &c);
            x = fmaf(2.0f, c, x); y = fmaf(2.0f, s, y); xs[2] = x; ys[2] = y;
            __sincosf(p.w, &s, &c);
            x = fmaf(2.0f, c, x); y = fmaf(2.0f, s, y); xs[3] = x; ys[3] = y;
        }

        // batched target-distance terms
        #pragma unroll
        for (int j = 0; j < 4; ++j) {
            float dx = tx - xs[j], dy = ty - ys[j];
            dist_sum += fast_sqrt(fmaf(dx, dx, dy * dy));
        }

        // batched in-box tests (per-lane box) + ballots
        bool ib[4];
        unsigned m[4];
        #pragma unroll
        for (int j = 0; j < 4; ++j)
            ib[j] = (fabsf(xs[j] - cbx) <= hbx) & (fabsf(ys[j] - cby) <= hby);
        #pragma unroll
        for (int j = 0; j < 4; ++j)
            m[j] = __ballot_sync(0xffffffffu, ib[j]);

        // compact appends (tagged with n-group)
        #pragma unroll
        for (int j = 0; j < 4; ++j) {
            if (ib[j]) {
                int slot = (head + pending + __popc(m[j] & lt_mask)) & (BUFCAP-1);
                s_buf[warp][slot] = make_float2(xs[j], ys[j]);
                s_grp[warp][slot] = (unsigned char)ng;
            }
            pending += __popc(m[j]);
        }

        // batched vehicle shfls (neighbor v+1 = lane+1), then terms
        float xn[4], yn[4];
        #pragma unroll
        for (int j = 0; j < 4; ++j) {
            xn[j] = __shfl_down_sync(0xffffffffu, xs[j], 1);
            yn[j] = __shfl_down_sync(0xffffffffu, ys[j], 1);
        }
        if (vact) {
            #pragma unroll
            for (int j = 0; j < 4; ++j) {
                float bxv = xn[j] - xs[j], byv = yn[j] - ys[j];
                float d2 = fmaf(bxv, bxv, byv * byv);
                if (d2 < 1.0f) { vinv += rsqrtf(d2); vcnt++; }   // VEH_R^2 = 1
            }
        }

        // drain (warp-uniform): 32 tagged points per pass
        while (pending >= 32) {
            __syncwarp();
            int slot = (head + lane) & (BUFCAP-1);
            float2 q = s_buf[warp][slot];
            int g = s_grp[warp][slot];
            #pragma unroll
            for (int o = 0; o < OO; ++o) {
                float ax = q.x - s_ox[warp][g][o];
                float ay = q.y - s_oy[warp][g][o];
                float d2o = fmaf(ax, ax, ay * ay);
                if (d2o < s_r2[warp][g][o]) { oinv += rsqrtf(d2o); ocnt++; }
            }
            head = (head + 32) & (BUFCAP-1);
            pending -= 32;
        }
    }

    // final flush
    if (pending > 0) {
        __syncwarp();
        if (lane < pending) {
            int slot = (head + lane) & (BUFCAP-1);
            float2 q = s_buf[warp][slot];
            int g = s_grp[warp][slot];
            #pragma unroll
            for (int o = 0; o < OO; ++o) {
                float ax = q.x - s_ox[warp][g][o];
                float ay = q.y - s_oy[warp][g][o];
                float d2o = fmaf(ax, ax, ay * ay);
                if (d2o < s_r2[warp][g][o]) { oinv += rsqrtf(d2o); ocnt++; }
            }
        }
    }

    // ---- warp -> block reduction ----
    dist_sum = warp_red_f(dist_sum);
    oinv     = warp_red_f(oinv);
    vinv     = warp_red_f(vinv);
    ocnt     = warp_red_i(ocnt);
    vcnt     = warp_red_i(vcnt);

    __shared__ float sd[WPB], so[WPB], sv[WPB];
    __shared__ int soc[WPB], svc[WPB];
    if (lane == 0) {
        sd[warp] = dist_sum; so[warp] = oinv; sv[warp] = vinv;
        soc[warp] = ocnt; svc[warp] = vcnt;
    }
    __syncthreads();
    if (warp == 0) {
        float d = (lane < WPB) ? sd[lane] : 0.0f;
        float a = (lane < WPB) ? so[lane] : 0.0f;
        float b = (lane < WPB) ? sv[lane] : 0.0f;
        int   c = (lane < WPB) ? soc[lane] : 0;
        int   e = (lane < WPB) ? svc[lane] : 0;
        d = warp_red_f(d); a = warp_red_f(a); b = warp_red_f(b);
        c = warp_red_i(c); e = warp_red_i(e);
        if (lane == 0) {
            g_pd[blockIdx.x] = d;
            g_po[blockIdx.x] = a;
            g_pv[blockIdx.x] = b;
            g_oc[blockIdx.x] = c;
            g_vc[blockIdx.x] = e;
        }
    }

    // ---- last-block finalize ----
    __shared__ bool isLast;
    __threadfence();
    if (threadIdx.x == 0) {
        unsigned int prev = atomicAdd(&g_done, 1u);
        isLast = (prev == NPART - 1);
    }
    __syncthreads();
    if (!isLast) return;

    float d = 0.0f, a = 0.0f, b = 0.0f;
    int c = 0, e = 0;
    #pragma unroll
    for (int i = 0; i < NPART / TPB; ++i) {
        int idx = threadIdx.x + i * TPB;
        d += g_pd[idx]; a += g_po[idx]; b += g_pv[idx];
        c += g_oc[idx]; e += g_vc[idx];
    }
    d = warp_red_f(d); a = warp_red_f(a); b = warp_red_f(b);
    c = warp_red_i(c); e = warp_red_i(e);
    if (lane == 0) {
        sd[warp] = d; so[warp] = a; sv[warp] = b; soc[warp] = c; svc[warp] = e;
    }
    __syncthreads();
    if (warp == 0) {
        d = (lane < WPB) ? sd[lane] : 0.0f;
        a = (lane < WPB) ? so[lane] : 0.0f;
        b = (lane < WPB) ? sv[lane] : 0.0f;
        c = (lane < WPB) ? soc[lane] : 0;
        e = (lane < WPB) ? svc[lane] : 0;
        d = warp_red_f(d); a = warp_red_f(a); b = warp_red_f(b);
        c = warp_red_i(c); e = warp_red_i(e);
        if (lane == 0) {
            double loss = (double)d / ((double)NN * VV * HH);   // DIST_COST=1
            if (c > 0) loss += ((double)a / (double)c) * 0.1;   // OBST_COST
            if (e > 0) loss += ((double)b / (double)e) * 0.1;   // VEH_COST
            out[0] = (float)loss;
            g_done = 0;   // reset for next graph replay
        }
    }
}

extern "C" void kernel_launch(void* const* d_in, const int* in_sizes, int n_in,
                              void* d_out, int out_size) {
    const float* pred   = (const float*)d_in[0];   // (N, V, H, 1) f32
    const float* inputs = (const float*)d_in[1];   // (N, 80) f32
    float* out = (float*)d_out;

    loss_kernel<<<NPART, TPB>>>(pred, inputs, out);
}

// round 13
// speedup vs baseline: 1.3012x; 1.0986x over previous
#include <cuda_runtime.h>

#define NN 8192
#define VV 8
#define OO 16
#define HH 128
#define ROW (4*VV + 3*OO)   // 80 floats per input row
#define TPB 128
#define WPB 4               // warps per block
#define NPW 4               // problem rows (n) per warp: lane = ng*8 + v
#define NPART (NN / (WPB * NPW))   // 512 blocks
#define BUFCAP 256          // power-of-2 ring (max pending 31+128=159)
#define OPAD 17             // obstacle array pad: 17g+o conflict-free

// Per-block partials (plain stores; no zeroing kernel)
__device__ float g_pd[NPART];
__device__ float g_po[NPART];
__device__ float g_pv[NPART];
__device__ int   g_oc[NPART];
__device__ int   g_vc[NPART];
__device__ unsigned int g_done;   // zero-init; last block resets each launch

__inline__ __device__ float warp_red_f(float v) {
    #pragma unroll
    for (int o = 16; o > 0; o >>= 1) v += __shfl_down_sync(0xffffffffu, v, o);
    return v;
}
__inline__ __device__ int warp_red_i(int v) {
    #pragma unroll
    for (int o = 16; o > 0; o >>= 1) v += __shfl_down_sync(0xffffffffu, v, o);
    return v;
}

__inline__ __device__ float fast_sqrt(float x) {
    float r;
    asm("sqrt.approx.f32 %0, %1;" : "=f"(r) : "f"(x));
    return r;
}

// One thread = one (n, v), walking all 128 steps serially (the chain is only
// an FMA: angles come from memory). Warp = 4 n-groups x 8 vehicles.
// Prediction loads are software-pipelined (prefetch distance 2) so 2-3
// 16B loads are in flight per thread: the R12 profile showed the exposed
// p4[i] load latency (MLP=1 at 14 warps/SM) was the dominant stall.
__global__ void __launch_bounds__(TPB) loss_kernel(
    const float* __restrict__ pred,     // (N, V, H) f32
    const float* __restrict__ inputs,   // (N, 80) f32
    float* __restrict__ out)
{
    const int warp = threadIdx.x >> 5;
    const int lane = threadIdx.x & 31;
    const int ng   = lane >> 3;          // n-group within warp (0..3)
    const int v    = lane & 7;           // vehicle
    const int n    = (blockIdx.x * WPB + warp) * NPW + ng;

    const float* row = inputs + (size_t)n * ROW;

    __shared__ float s_ox[WPB][NPW][OPAD];
    __shared__ float s_oy[WPB][NPW][OPAD];
    __shared__ float s_r2[WPB][NPW][OPAD];
    __shared__ float2 s_buf[WPB][BUFCAP];
    __shared__ unsigned char s_grp[WPB][BUFCAP];

    // ---- obstacles -> smem (64 obstacle slots, 2 per lane) ----
    #pragma unroll
    for (int idx = lane; idx < NPW * OO; idx += 32) {
        int g = idx >> 4, o = idx & 15;
        const float* orow = inputs + (size_t)((blockIdx.x * WPB + warp) * NPW + g) * ROW
                            + 4 * VV + 3 * o;
        float cx = orow[0], cy = orow[1];
        float r  = orow[2] + 1.0f;               // + OBST_RADIUS
        s_ox[warp][g][o] = cx;
        s_oy[warp][g][o] = cy;
        s_r2[warp][g][o] = (r > 0.0f) ? r * r : -1.0f;
    }
    __syncwarp();

    // ---- per-lane prune box for its own n-group (broadcast LDS reads) ----
    float mnx = 1e30f, mxx = -1e30f, mny = 1e30f, mxy = -1e30f, rmx = -1e30f;
    #pragma unroll
    for (int o = 0; o < OO; ++o) {
        float cx = s_ox[warp][ng][o];
        float cy = s_oy[warp][ng][o];
        float r2 = s_r2[warp][ng][o];
        mnx = fminf(mnx, cx); mxx = fmaxf(mxx, cx);
        mny = fminf(mny, cy); mxy = fmaxf(mxy, cy);
        rmx = fmaxf(rmx, r2);
    }
    rmx = (rmx > 0.0f) ? fast_sqrt(rmx) : 0.0f;   // max effective radius
    const float cbx = 0.5f * (mnx + mxx), hbx = 0.5f * (mxx - mnx) + rmx;
    const float cby = 0.5f * (mny + mxy), hby = 0.5f * (mxy - mny) + rmx;

    // ---- vehicle start / target (vectorized: 16B-aligned) ----
    const float4 vd = *(const float4*)(row + 4 * v);
    float x = vd.x, y = vd.y;
    const float tx = vd.z, ty = vd.w;

    const float4* p4 = (const float4*)(pred + (size_t)(n * VV + v) * HH);

    // ---- single pass: 32 batches of 4 steps; loads pipelined dist 2 ----
    float dist_sum = 0.0f, oinv = 0.0f, vinv = 0.0f;
    int ocnt = 0, vcnt = 0;
    int head = 0, pending = 0;              // warp-uniform ring state
    const unsigned lt_mask = (1u << lane) - 1u;
    const bool vact = (v < 7);

    float4 pa = __ldcs(&p4[0]);
    float4 pb = __ldcs(&p4[1]);

    #pragma unroll 1
    for (int i = 0; i < HH / 4; ++i) {
        // issue the i+2 load before any compute on pa
        float4 pc = __ldcs(&p4[(i + 2 < HH / 4) ? i + 2 : i]);
        float4 p = pa;
        pa = pb; pb = pc;

        // serial position chain: only the fmaf is dependent (lat 4)
        float xs[4], ys[4];
        {
            float s, c;
            __sincosf(p.x, &s, &c);
            x = fmaf(2.0f, c, x); y = fmaf(2.0f, s, y); xs[0] = x; ys[0] = y;
            __sincosf(p.y, &s, &c);
            x = fmaf(2.0f, c, x); y = fmaf(2.0f, s, y); xs[1] = x; ys[1] = y;
            __sincosf(p.z, &s, &c);
            x = fmaf(2.0f, c, x); y = fmaf(2.0f, s, y); xs[2] = x; ys[2] = y;
            __sincosf(p.w, &s, &c);
            x = fmaf(2.0f, c, x); y = fmaf(2.0f, s, y); xs[3] = x; ys[3] = y;
        }

        // batched target-distance terms
        #pragma unroll
        for (int j = 0; j < 4; ++j) {
            float dx = tx - xs[j], dy = ty - ys[j];
            dist_sum += fast_sqrt(fmaf(dx, dx, dy * dy));
        }

        // batched in-box tests (per-lane box) + ballots
        bool ib[4];
        unsigned m[4];
        #pragma unroll
        for (int j = 0; j < 4; ++j)
            ib[j] = (fabsf(xs[j] - cbx) <= hbx) & (fabsf(ys[j] - cby) <= hby);
        #pragma unroll
        for (int j = 0; j < 4; ++j)
            m[j] = __ballot_sync(0xffffffffu, ib[j]);

        // compact appends (tagged with n-group)
        #pragma unroll
        for (int j = 0; j < 4; ++j) {
            if (ib[j]) {
                int slot = (head + pending + __popc(m[j] & lt_mask)) & (BUFCAP-1);
                s_buf[warp][slot] = make_float2(xs[j], ys[j]);
                s_grp[warp][slot] = (unsigned char)ng;
            }
            pending += __popc(m[j]);
        }

        // batched vehicle shfls (neighbor v+1 = lane+1), then terms
        float xn[4], yn[4];
        #pragma unroll
        for (int j = 0; j < 4; ++j) {
            xn[j] = __shfl_down_sync(0xffffffffu, xs[j], 1);
            yn[j] = __shfl_down_sync(0xffffffffu, ys[j], 1);
        }
        if (vact) {
            #pragma unroll
            for (int j = 0; j < 4; ++j) {
                float bxv = xn[j] - xs[j], byv = yn[j] - ys[j];
                float d2 = fmaf(bxv, bxv, byv * byv);
                if (d2 < 1.0f) { vinv += rsqrtf(d2); vcnt++; }   // VEH_R^2 = 1
            }
        }

        // drain (warp-uniform): 32 tagged points per pass
        while (pending >= 32) {
            __syncwarp();
            int slot = (head + lane) & (BUFCAP-1);
            float2 q = s_buf[warp][slot];
            int g = s_grp[warp][slot];
            #pragma unroll
            for (int o = 0; o < OO; ++o) {
                float ax = q.x - s_ox[warp][g][o];
                float ay = q.y - s_oy[warp][g][o];
                float d2o = fmaf(ax, ax, ay * ay);
                if (d2o < s_r2[warp][g][o]) { oinv += rsqrtf(d2o); ocnt++; }
            }
            head = (head + 32) & (BUFCAP-1);
            pending -= 32;
        }
    }

    // final flush
    if (pending > 0) {
        __syncwarp();
        if (lane < pending) {
            int slot = (head + lane) & (BUFCAP-1);
            float2 q = s_buf[warp][slot];
            int g = s_grp[warp][slot];
            #pragma unroll
            for (int o = 0; o < OO; ++o) {
                float ax = q.x - s_ox[warp][g][o];
                float ay = q.y - s_oy[warp][g][o];
                float d2o = fmaf(ax, ax, ay * ay);
                if (d2o < s_r2[warp][g][o]) { oinv += rsqrtf(d2o); ocnt++; }
            }
        }
    }

    // ---- warp -> block reduction ----
    dist_sum = warp_red_f(dist_sum);
    oinv     = warp_red_f(oinv);
    vinv     = warp_red_f(vinv);
    ocnt     = warp_red_i(ocnt);
    vcnt     = warp_red_i(vcnt);

    __shared__ float sd[WPB], so[WPB], sv[WPB];
    __shared__ int soc[WPB], svc[WPB];
    if (lane == 0) {
        sd[warp] = dist_sum; so[warp] = oinv; sv[warp] = vinv;
        soc[warp] = ocnt; svc[warp] = vcnt;
    }
    __syncthreads();
    if (warp == 0) {
        float d = (lane < WPB) ? sd[lane] : 0.0f;
        float a = (lane < WPB) ? so[lane] : 0.0f;
        float b = (lane < WPB) ? sv[lane] : 0.0f;
        int   c = (lane < WPB) ? soc[lane] : 0;
        int   e = (lane < WPB) ? svc[lane] : 0;
        d = warp_red_f(d); a = warp_red_f(a); b = warp_red_f(b);
        c = warp_red_i(c); e = warp_red_i(e);
        if (lane == 0) {
            g_pd[blockIdx.x] = d;
            g_po[blockIdx.x] = a;
            g_pv[blockIdx.x] = b;
            g_oc[blockIdx.x] = c;
            g_vc[blockIdx.x] = e;
        }
    }

    // ---- last-block finalize ----
    __shared__ bool isLast;
    __threadfence();
    if (threadIdx.x == 0) {
        unsigned int prev = atomicAdd(&g_done, 1u);
        isLast = (prev == NPART - 1);
    }
    __syncthreads();
    if (!isLast) return;

    float d = 0.0f, a = 0.0f, b = 0.0f;
    int c = 0, e = 0;
    #pragma unroll
    for (int i = 0; i < NPART / TPB; ++i) {
        int idx = threadIdx.x + i * TPB;
        d += g_pd[idx]; a += g_po[idx]; b += g_pv[idx];
        c += g_oc[idx]; e += g_vc[idx];
    }
    d = warp_red_f(d); a = warp_red_f(a); b = warp_red_f(b);
    c = warp_red_i(c); e = warp_red_i(e);
    if (lane == 0) {
        sd[warp] = d; so[warp] = a; sv[warp] = b; soc[warp] = c; svc[warp] = e;
    }
    __syncthreads();
    if (warp == 0) {
        d = (lane < WPB) ? sd[lane] : 0.0f;
        a = (lane < WPB) ? so[lane] : 0.0f;
        b = (lane < WPB) ? sv[lane] : 0.0f;
        c = (lane < WPB) ? soc[lane] : 0;
        e = (lane < WPB) ? svc[lane] : 0;
        d = warp_red_f(d); a = warp_red_f(a); b = warp_red_f(b);
        c = warp_red_i(c); e = warp_red_i(e);
        if (lane == 0) {
            double loss = (double)d / ((double)NN * VV * HH);   // DIST_COST=1
            if (c > 0) loss += ((double)a / (double)c) * 0.1;   // OBST_COST
            if (e > 0) loss += ((double)b / (double)e) * 0.1;   // VEH_COST
            out[0] = (float)loss;
            g_done = 0;   // reset for next graph replay
        }
    }
}

extern "C" void kernel_launch(void* const* d_in, const int* in_sizes, int n_in,
                              void* d_out, int out_size) {
    const float* pred   = (const float*)d_in[0];   // (N, V, H, 1) f32
    const float* inputs = (const float*)d_in[1];   // (N, 80) f32
    float* out = (float*)d_out;

    loss_kernel<<<NPART, TPB>>>(pred, inputs, out);
}